// round 7
// baseline (speedup 1.0000x reference)
#include <cuda_runtime.h>
#include <cuda_fp16.h>
#include <cstdint>

using u8 = uint8_t;
#define DEVINLINE __device__ __forceinline__

static constexpr int CH    = 512;
static constexpr int HWDIM = 1024;
static constexpr int BATCH = 32;
static constexpr int NALL  = BATCH * HWDIM;   // 32768

static constexpr float WO_SCALE   = 134217728.f;          // 2^27
static constexpr float WO_UNSCALE = 7.450580596923828e-9f; // 2^-27

// ---------------- scratch (16B-aligned for cp.async / uint4) -----------------
__device__ __align__(128) u8    g_W [4 * CH * CH];
__device__ __align__(128) u8    g_XT[(size_t)NALL * CH];
__device__ __align__(128) u8    g_QK[(size_t)NALL * 2 * CH];
__device__ __align__(128) u8    g_V [(size_t)CH * NALL];
__device__ __align__(128) u8    g_P [(size_t)BATCH * HWDIM * HWDIM];
__device__ __align__(128) float g_RS[NALL];
__device__ __align__(128) u8    g_HT[(size_t)NALL * CH];

// ---------------- helpers ------------------------------------------------------
DEVINLINE uint16_t f32x2_e4m3(float lo, float hi) {
    uint16_t d;
    asm("cvt.rn.satfinite.e4m3x2.f32 %0, %1, %2;" : "=h"(d) : "f"(hi), "f"(lo));
    return d;   // low byte = lo, high byte = hi
}
DEVINLINE float2 e4m3x2_f32(uint16_t s) {
    uint32_t h;
    asm("cvt.rn.f16x2.e4m3x2 %0, %1;" : "=r"(h) : "h"(s));
    __half2 hh = *reinterpret_cast<__half2*>(&h);
    return __half22float2(hh);
}

DEVINLINE void ldsm4(uint32_t& r0, uint32_t& r1, uint32_t& r2, uint32_t& r3,
                     const u8* p) {
    uint32_t addr = (uint32_t)__cvta_generic_to_shared(p);
    asm volatile("ldmatrix.sync.aligned.m8n8.x4.shared.b16 {%0,%1,%2,%3}, [%4];"
                 : "=r"(r0), "=r"(r1), "=r"(r2), "=r"(r3) : "r"(addr));
}

DEVINLINE void mma_fp8(float c[4], const uint32_t a[4], const uint32_t b[2]) {
    asm volatile("mma.sync.aligned.m16n8k32.row.col.f32.e4m3.e4m3.f32 "
                 "{%0,%1,%2,%3},{%4,%5,%6,%7},{%8,%9},{%0,%1,%2,%3};"
                 : "+f"(c[0]), "+f"(c[1]), "+f"(c[2]), "+f"(c[3])
                 : "r"(a[0]), "r"(a[1]), "r"(a[2]), "r"(a[3]),
                   "r"(b[0]), "r"(b[1]));
}

DEVINLINE void cp16(u8* dst, const u8* src) {
    uint32_t d = (uint32_t)__cvta_generic_to_shared(dst);
    asm volatile("cp.async.cg.shared.global [%0], [%1], 16;" :: "r"(d), "l"(src));
}
DEVINLINE void cp_commit() { asm volatile("cp.async.commit_group;"); }
template<int N> DEVINLINE void cp_wait() {
    asm volatile("cp.async.wait_group %0;" :: "n"(N));
}

// ---------------- prep kernels ---------------------------------------------------
__global__ void convert_w_kernel(const float* __restrict__ wq, const float* __restrict__ wk,
                                 const float* __restrict__ wv, const float* __restrict__ wo,
                                 u8* __restrict__ W) {
    int i = (blockIdx.x * blockDim.x + threadIdx.x) * 2;
    *(uint16_t*)(W + i)              = f32x2_e4m3(wq[i], wq[i + 1]);
    *(uint16_t*)(W + i + CH * CH)    = f32x2_e4m3(wk[i], wk[i + 1]);
    *(uint16_t*)(W + i + 2 * CH * CH) = f32x2_e4m3(wv[i], wv[i + 1]);
    *(uint16_t*)(W + i + 3 * CH * CH) =
        f32x2_e4m3(wo[i] * WO_SCALE, wo[i + 1] * WO_SCALE);
}

// x [B][C][HW] fp32 -> XT [B*HW][C] e4m3
__global__ void xt_kernel(const float* __restrict__ x, u8* __restrict__ XT) {
    __shared__ float tile[32][33];
    const int b  = blockIdx.z;
    const int s0 = blockIdx.x * 32;
    const int c0 = blockIdx.y * 32;
    const int tx = threadIdx.x, ty = threadIdx.y;
    tile[ty][tx] = x[((size_t)b * CH + c0 + ty) * HWDIM + s0 + tx];
    __syncthreads();
    // each thread pair writes 2 bytes via u16 for alignment: do per-thread byte store
    if ((tx & 1) == 0) {
        uint16_t v = f32x2_e4m3(tile[tx][ty], tile[tx + 1][ty]);
        *(uint16_t*)(XT + ((size_t)b * HWDIM + s0 + ty) * CH + c0 + tx) = v;
    }
}

// 1/rowsum of exp-scores P (e4m3); warp per row
__global__ void rowsum_kernel(const u8* __restrict__ P, float* __restrict__ RS) {
    const int row  = blockIdx.x * 8 + (threadIdx.x >> 5);
    const int lane = threadIdx.x & 31;
    const uint4* p = (const uint4*)(P + (size_t)row * HWDIM);
    float s = 0.f;
    #pragma unroll
    for (int j = 0; j < 2; ++j) {
        uint4 v = p[lane + j * 32];
        const uint16_t* h = (const uint16_t*)&v;
        #pragma unroll
        for (int t = 0; t < 8; ++t) { float2 f = e4m3x2_f32(h[t]); s += f.x + f.y; }
    }
    #pragma unroll
    for (int o = 16; o > 0; o >>= 1) s += __shfl_xor_sync(0xffffffffu, s, o);
    if (lane == 0) RS[row] = 1.f / s;
}

// ---------------- FP8 GEMM: C[m,n] = sum_k A[m,k]*B[n,k] -----------------------
// A,B e4m3 k-major. CTA tile 128x128, BK=64 bytes; 8 warps of 64x32, f32 acc.
// 3-stage cp.async pipeline, one barrier per k-tile.
// EPI 0: fp8 out, dual col-bias   1: fp8 out, row bias   2: fp8 = exp(acc*scale)
// EPI 3: fp32 [b][r][s] : acc*WO_UNSCALE + row bias + residual
// EPI 4: fp8 out, row-scaled by aux[z*1024+r]
template<int EPI>
__global__ void __launch_bounds__(256, 2)
gemm_kernel(const u8* __restrict__ A, const u8* __restrict__ B,
            void* __restrict__ Cout,
            int K, int lda, int ldb, int ldc,
            size_t sA_batch, size_t sB_batch, size_t sC_batch,
            const float* __restrict__ bias1, const float* __restrict__ bias2,
            const float* __restrict__ aux, float scale)
{
    constexpr int BM = 128, BN = 128, BK = 64;
    constexpr int STAGES = 3;
    constexpr int LDSB = BK + 16;               // 80 B rows -> conflict-free ldsm
    constexpr int ASZ = BM * LDSB;              // 10240 B
    constexpr int BSZ = BN * LDSB;
    extern __shared__ u8 smem[];
    u8* sA = smem;                    // [STAGES][ASZ]
    u8* sB = smem + STAGES * ASZ;     // [STAGES][BSZ]

    const int tid  = threadIdx.x;
    const int lane = tid & 31;
    const int warp = tid >> 5;
    const int wm   = warp >> 2;       // 0..1  (64 rows)
    const int wn   = warp & 3;        // 0..3  (32 cols)
    const int bm0  = blockIdx.y * BM;
    const int bn0  = blockIdx.x * BN;
    const int z    = blockIdx.z;

    const u8* Ab = A + (size_t)z * sA_batch;
    const u8* Bb = B + (size_t)z * sB_batch;

    // producers: 128 rows x 64 B = 8x16B chunks/row; 512 chunks per operand,
    // 256 threads -> 2 chunks each (at +0 and +16 of a 32B span)
    const int prow = tid >> 1;
    const int pcol = (tid & 1) * 32;

    const u8* gA = Ab + (size_t)(bm0 + prow) * lda + pcol;
    const u8* gB = Bb + (size_t)(bn0 + prow) * ldb + pcol;
    u8* swA = sA + prow * LDSB + pcol;
    u8* swB = sB + prow * LDSB + pcol;

    const int nk = K / BK;

    auto load_stage = [&](int stg, int kt) {
        const int ko = kt * BK;
        u8* dA = swA + stg * ASZ;
        u8* dB = swB + stg * BSZ;
        cp16(dA,      gA + ko);
        cp16(dA + 16, gA + ko + 16);
        cp16(dB,      gB + ko);
        cp16(dB + 16, gB + ko + 16);
        cp_commit();
    };

    load_stage(0, 0);
    load_stage(1, 1);      // nk >= 8 always

    float acc[4][4][4];
    #pragma unroll
    for (int i = 0; i < 4; ++i)
        #pragma unroll
        for (int j = 0; j < 4; ++j)
            #pragma unroll
            for (int l = 0; l < 4; ++l) acc[i][j][l] = 0.f;

    const int a_base = (wm * 64 + (lane & 15)) * LDSB + (lane >> 4) * 16;
    const int b_base = (wn * 32 + (lane & 7) + ((lane >> 4) & 1) * 8) * LDSB
                     + ((lane >> 3) & 1) * 16;

    int s_cur = 0, s_nxt2 = 2;

    for (int kt = 0; kt < nk; ++kt) {
        if (kt + 2 <= nk) cp_wait<1>(); else cp_wait<0>();
        __syncthreads();

        if (kt + 2 < nk) load_stage(s_nxt2, kt + 2);

        const u8* ca = sA + s_cur * ASZ;
        const u8* cb = sB + s_cur * BSZ;
        #pragma unroll
        for (int ks = 0; ks < 2; ++ks) {         // 32-byte (k32) halves
            uint32_t af[4][4];
            #pragma unroll
            for (int mf = 0; mf < 4; ++mf)
                ldsm4(af[mf][0], af[mf][1], af[mf][2], af[mf][3],
                      &ca[a_base + mf * 16 * LDSB + ks * 32]);
            uint32_t bg[4][2];
            #pragma unroll
            for (int pr = 0; pr < 2; ++pr)
                ldsm4(bg[2 * pr][0], bg[2 * pr][1], bg[2 * pr + 1][0], bg[2 * pr + 1][1],
                      &cb[b_base + pr * 16 * LDSB + ks * 32]);
            #pragma unroll
            for (int mf = 0; mf < 4; ++mf)
                #pragma unroll
                for (int nf = 0; nf < 4; ++nf)
                    mma_fp8(acc[mf][nf], af[mf], bg[nf]);
        }

        s_cur  = (s_cur == STAGES - 1)  ? 0 : s_cur + 1;
        s_nxt2 = (s_nxt2 == STAGES - 1) ? 0 : s_nxt2 + 1;
    }

    const int r_base = bm0 + wm * 64 + (lane >> 2);
    const int c_base = bn0 + wn * 32 + ((lane & 3) << 1);

    #pragma unroll
    for (int mf = 0; mf < 4; ++mf) {
        #pragma unroll
        for (int nf = 0; nf < 4; ++nf) {
            const int r = r_base + mf * 16;
            const int c = c_base + nf * 8;
            const float* a4 = acc[mf][nf];

            if (EPI == 0) {
                u8* outp = (u8*)Cout + (size_t)z * sC_batch;
                const float b0 = (c < 512)     ? bias1[c]     : bias2[c - 512];
                const float b1 = (c + 1 < 512) ? bias1[c + 1] : bias2[c + 1 - 512];
                *(uint16_t*)(outp + (size_t)r * ldc + c) =
                    f32x2_e4m3(a4[0] + b0, a4[1] + b1);
                *(uint16_t*)(outp + (size_t)(r + 8) * ldc + c) =
                    f32x2_e4m3(a4[2] + b0, a4[3] + b1);
            } else if (EPI == 1) {
                u8* outp = (u8*)Cout + (size_t)z * sC_batch;
                const float rb0 = bias1[r];
                const float rb1 = bias1[r + 8];
                *(uint16_t*)(outp + (size_t)r * ldc + c) =
                    f32x2_e4m3(a4[0] + rb0, a4[1] + rb0);
                *(uint16_t*)(outp + (size_t)(r + 8) * ldc + c) =
                    f32x2_e4m3(a4[2] + rb1, a4[3] + rb1);
            } else if (EPI == 2) {
                u8* outp = (u8*)Cout + (size_t)z * sC_batch;
                *(uint16_t*)(outp + (size_t)r * ldc + c) =
                    f32x2_e4m3(__expf(a4[0] * scale), __expf(a4[1] * scale));
                *(uint16_t*)(outp + (size_t)(r + 8) * ldc + c) =
                    f32x2_e4m3(__expf(a4[2] * scale), __expf(a4[3] * scale));
            } else if (EPI == 4) {
                u8* outp = (u8*)Cout + (size_t)z * sC_batch;
                const float rs0 = aux[z * HWDIM + r];
                const float rs1 = aux[z * HWDIM + r + 8];
                *(uint16_t*)(outp + (size_t)r * ldc + c) =
                    f32x2_e4m3(a4[0] * rs0, a4[1] * rs0);
                *(uint16_t*)(outp + (size_t)(r + 8) * ldc + c) =
                    f32x2_e4m3(a4[2] * rs1, a4[3] * rs1);
            } else {   // EPI == 3 : final fp32 out + residual
                float* outp = (float*)Cout;
                const int bb = c >> 10;
                const int s  = c & 1023;
                const size_t i0 = (size_t)bb * (CH * HWDIM) + (size_t)r * HWDIM + s;
                const size_t i1 = i0 + 8 * HWDIM;
                const float br0 = bias1[r];
                const float br1 = bias1[r + 8];
                const float2 x0 = *(const float2*)(aux + i0);
                const float2 x1 = *(const float2*)(aux + i1);
                *(float2*)(outp + i0) = make_float2(a4[0] * WO_UNSCALE + br0 + x0.x,
                                                    a4[1] * WO_UNSCALE + br0 + x0.y);
                *(float2*)(outp + i1) = make_float2(a4[2] * WO_UNSCALE + br1 + x1.x,
                                                    a4[3] * WO_UNSCALE + br1 + x1.y);
            }
        }
    }
}

// ---------------- launch -----------------------------------------------------------
static constexpr int GEMM_SMEM = 3 * (128 * 80 + 128 * 80);   // 61440 B

extern "C" void kernel_launch(void* const* d_in, const int* in_sizes, int n_in,
                              void* d_out, int out_size)
{
    (void)in_sizes; (void)n_in; (void)out_size;
    const float* x  = (const float*)d_in[0];
    const float* Wq = (const float*)d_in[1];
    const float* bq = (const float*)d_in[2];
    const float* Wk = (const float*)d_in[3];
    const float* bk = (const float*)d_in[4];
    const float* Wv = (const float*)d_in[5];
    const float* bv = (const float*)d_in[6];
    const float* Wo = (const float*)d_in[7];
    const float* bo = (const float*)d_in[8];
    float* out = (float*)d_out;

    u8 *pW, *pXT, *pQK, *pV, *pP, *pHT;
    float *pRS;
    cudaGetSymbolAddress((void**)&pW,  g_W);
    cudaGetSymbolAddress((void**)&pXT, g_XT);
    cudaGetSymbolAddress((void**)&pQK, g_QK);
    cudaGetSymbolAddress((void**)&pV,  g_V);
    cudaGetSymbolAddress((void**)&pP,  g_P);
    cudaGetSymbolAddress((void**)&pRS, g_RS);
    cudaGetSymbolAddress((void**)&pHT, g_HT);

    cudaFuncSetAttribute(gemm_kernel<0>, cudaFuncAttributeMaxDynamicSharedMemorySize, GEMM_SMEM);
    cudaFuncSetAttribute(gemm_kernel<1>, cudaFuncAttributeMaxDynamicSharedMemorySize, GEMM_SMEM);
    cudaFuncSetAttribute(gemm_kernel<2>, cudaFuncAttributeMaxDynamicSharedMemorySize, GEMM_SMEM);
    cudaFuncSetAttribute(gemm_kernel<3>, cudaFuncAttributeMaxDynamicSharedMemorySize, GEMM_SMEM);
    cudaFuncSetAttribute(gemm_kernel<4>, cudaFuncAttributeMaxDynamicSharedMemorySize, GEMM_SMEM);

    // prep
    convert_w_kernel<<<(CH * CH / 2) / 256, 256>>>(Wq, Wk, Wv, Wo, pW);
    xt_kernel<<<dim3(HWDIM / 32, CH / 32, BATCH), dim3(32, 32)>>>(x, pXT);

    // QK = XT * [Wq|Wk]^T : M=32768, N=1024, K=512
    gemm_kernel<0><<<dim3(1024 / 128, NALL / 128, 1), 256, GEMM_SMEM>>>(
        pXT, pW, pQK, CH, CH, CH, 1024, 0, 0, 0, bq, bk, nullptr, 1.f);

    // V = Wv * X^T (+bv rows) : M=512, N=32768 -> [c][token]
    gemm_kernel<1><<<dim3(NALL / 128, CH / 128, 1), 256, GEMM_SMEM>>>(
        pW + 2 * CH * CH, pXT, pV, CH, CH, CH, NALL, 0, 0, 0, bv, nullptr, nullptr, 1.f);

    // P_b = exp(scale * Q_b K_b^T) : per batch M=N=1024, K=512
    gemm_kernel<2><<<dim3(1024 / 128, HWDIM / 128, BATCH), 256, GEMM_SMEM>>>(
        pQK, pQK + 512, pP, CH, 1024, 1024, HWDIM,
        (size_t)HWDIM * 1024, (size_t)HWDIM * 1024, (size_t)HWDIM * HWDIM,
        nullptr, nullptr, nullptr, 0.04419417382415922f);

    // 1/rowsums of P
    rowsum_kernel<<<NALL / 8, 256>>>(pP, pRS);

    // HT_b = (P_b * V_b^T) * rsinv : M=1024, N=512, K=1024
    gemm_kernel<4><<<dim3(CH / 128, HWDIM / 128, BATCH), 256, GEMM_SMEM>>>(
        pP, pV, pHT, HWDIM, HWDIM, NALL, CH,
        (size_t)HWDIM * HWDIM, (size_t)HWDIM, (size_t)HWDIM * CH,
        nullptr, nullptr, pRS, 1.f);

    // O = Wo_scaled * HT^T, unscale + bo + x : M=512, N=32768 -> [B][C][H][W]
    gemm_kernel<3><<<dim3(NALL / 128, CH / 128, 1), 256, GEMM_SMEM>>>(
        pW + 3 * CH * CH, pHT, out, CH, CH, CH, 0,
        0, 0, 0, bo, nullptr, x, 1.f);
}

// round 8
// speedup vs baseline: 1.0379x; 1.0379x over previous
#include <cuda_runtime.h>
#include <cuda_fp16.h>
#include <cstdint>

using f16 = __half;
#define DEVINLINE __device__ __forceinline__

static constexpr int CH    = 512;
static constexpr int HWDIM = 1024;
static constexpr int BATCH = 32;
static constexpr int NALL  = BATCH * HWDIM;   // 32768

static constexpr float WO_SCALE   = 4096.f;
static constexpr float WO_UNSCALE = 1.f / 4096.f;

// ---------------- scratch ----------------------------------------------------
__device__ f16   g_W [4 * CH * CH];
__device__ f16   g_XT[(size_t)NALL * CH];
__device__ f16   g_QK[(size_t)NALL * 2 * CH];
__device__ f16   g_V [(size_t)CH * NALL];
__device__ f16   g_P [(size_t)BATCH * HWDIM * HWDIM];
__device__ f16   g_HT[(size_t)NALL * CH];

// ---------------- helpers ------------------------------------------------------
DEVINLINE void ldsm4(uint32_t& r0, uint32_t& r1, uint32_t& r2, uint32_t& r3,
                     const f16* p) {
    uint32_t addr = (uint32_t)__cvta_generic_to_shared(p);
    asm volatile("ldmatrix.sync.aligned.m8n8.x4.shared.b16 {%0,%1,%2,%3}, [%4];"
                 : "=r"(r0), "=r"(r1), "=r"(r2), "=r"(r3) : "r"(addr));
}

DEVINLINE void mma_f16(uint32_t c[2], const uint32_t a[4], const uint32_t b[2]) {
    asm volatile("mma.sync.aligned.m16n8k16.row.col.f16.f16.f16.f16 "
                 "{%0,%1},{%2,%3,%4,%5},{%6,%7},{%0,%1};"
                 : "+r"(c[0]), "+r"(c[1])
                 : "r"(a[0]), "r"(a[1]), "r"(a[2]), "r"(a[3]),
                   "r"(b[0]), "r"(b[1]));
}

DEVINLINE void cp16(f16* dst, const f16* src) {
    uint32_t d = (uint32_t)__cvta_generic_to_shared(dst);
    asm volatile("cp.async.cg.shared.global [%0], [%1], 16;" :: "r"(d), "l"(src));
}
DEVINLINE void cp_commit() { asm volatile("cp.async.commit_group;"); }
template<int N> DEVINLINE void cp_wait() {
    asm volatile("cp.async.wait_group %0;" :: "n"(N));
}

DEVINLINE float hsum2(uint32_t h) {
    float2 f = __half22float2(*reinterpret_cast<const __half2*>(&h));
    return f.x + f.y;
}

// ---------------- prep kernels ---------------------------------------------------
__global__ void convert_w_kernel(const float* __restrict__ wq, const float* __restrict__ wk,
                                 const float* __restrict__ wv, const float* __restrict__ wo,
                                 f16* __restrict__ W) {
    int i = blockIdx.x * blockDim.x + threadIdx.x;
    W[i]               = __float2half(wq[i]);
    W[i + CH * CH]     = __float2half(wk[i]);
    W[i + 2 * CH * CH] = __float2half(wv[i]);
    W[i + 3 * CH * CH] = __float2half(wo[i] * WO_SCALE);
}

// x [B][C][HW] fp32 -> XT [B*HW][C] f16
__global__ void xt_kernel(const float* __restrict__ x, f16* __restrict__ XT) {
    __shared__ float tile[32][33];
    const int b  = blockIdx.z;
    const int s0 = blockIdx.x * 32;
    const int c0 = blockIdx.y * 32;
    const int tx = threadIdx.x, ty = threadIdx.y;
    tile[ty][tx] = x[((size_t)b * CH + c0 + ty) * HWDIM + s0 + tx];
    __syncthreads();
    XT[((size_t)b * HWDIM + s0 + ty) * CH + c0 + tx] = __float2half(tile[tx][ty]);
}

// ---------------- GEMM: C[m,n] = sum_k A[m,k]*B[n,k], f16 accum -----------------
// CTA tile 128x256 (BK=32); 8 warps of 64x64. 3-stage cp.async pipeline,
// one barrier per k-tile.
// EPI 0: f16 out, dual col-bias   1: f16 out, row bias   2: f16 = exp(acc*scale)
// EPI 3: fp32 [b][r][s] : acc*WO_UNSCALE + row bias + residual
// EPI 4: f16 out, row-scaled by 1/rowsum(A) computed INLINE from A fragments
template<int EPI>
__global__ void __launch_bounds__(256, 2)
gemm_kernel(const f16* __restrict__ A, const f16* __restrict__ B,
            void* __restrict__ Cout,
            int K, int lda, int ldb, int ldc,
            size_t sA_batch, size_t sB_batch, size_t sC_batch,
            const float* __restrict__ bias1, const float* __restrict__ bias2,
            const float* __restrict__ aux, float scale)
{
    constexpr int BM = 128, BN = 256, BK = 32;
    constexpr int STAGES = 3;
    constexpr int LDS = BK + 8;                 // 40 halves = 80 B rows
    constexpr int ASZ = BM * LDS;
    constexpr int BSZ = BN * LDS;
    extern __shared__ f16 smem[];
    f16* sA = smem;                    // [STAGES][ASZ]
    f16* sB = smem + STAGES * ASZ;     // [STAGES][BSZ]

    __shared__ float rs_sh[BM];        // row sums (EPI 4 only)

    const int tid  = threadIdx.x;
    const int lane = tid & 31;
    const int warp = tid >> 5;
    const int wm   = warp >> 2;       // 0..1   (64 rows)
    const int wn   = warp & 3;        // 0..3   (64 cols)
    const int bm0  = blockIdx.y * BM;
    const int bn0  = blockIdx.x * BN;
    const int z    = blockIdx.z;

    const f16* Ab = A + (size_t)z * sA_batch;
    const f16* Bb = B + (size_t)z * sB_batch;

    const int arow = tid >> 1;
    const int acol = (tid & 1) * 16;
    const int brow = tid >> 2;
    const int bcol = (tid & 3) * 8;

    const f16* gA = Ab + (size_t)(bm0 + arow) * lda + acol;
    const f16* gB = Bb + (size_t)(bn0 + brow) * ldb + bcol;
    f16* swA = sA + arow * LDS + acol;
    f16* swB = sB + brow * LDS + bcol;

    const int nk = K / BK;

    auto load_stage = [&](int stg, int kt) {
        const int ko = kt * BK;
        f16* dA = swA + stg * ASZ;
        f16* dB = swB + stg * BSZ;
        cp16(dA,     gA + ko);
        cp16(dA + 8, gA + ko + 8);
        #pragma unroll
        for (int i = 0; i < 4; ++i)
            cp16(dB + i * 64 * LDS, gB + (size_t)i * 64 * ldb + ko);
        cp_commit();
    };

    load_stage(0, 0);
    load_stage(1, 1);        // nk >= 16 always

    uint32_t acc[4][8][2];
    #pragma unroll
    for (int i = 0; i < 4; ++i)
        #pragma unroll
        for (int j = 0; j < 8; ++j) { acc[i][j][0] = 0u; acc[i][j][1] = 0u; }

    // inline row-sum accumulators (live only in EPI==4 instantiation)
    float rsum[4][2];
    if (EPI == 4) {
        #pragma unroll
        for (int i = 0; i < 4; ++i) { rsum[i][0] = 0.f; rsum[i][1] = 0.f; }
    }

    const int a_base = (wm * 64 + (lane & 15)) * LDS + (lane >> 4) * 8;
    const int b_base = (wn * 64 + (lane & 7) + ((lane >> 4) & 1) * 8) * LDS
                     + ((lane >> 3) & 1) * 8;

    int s_cur = 0, s_nxt2 = 2;

    for (int kt = 0; kt < nk; ++kt) {
        if (kt + 2 <= nk) cp_wait<1>(); else cp_wait<0>();
        __syncthreads();

        if (kt + 2 < nk) load_stage(s_nxt2, kt + 2);

        const f16* ca = sA + s_cur * ASZ;
        const f16* cb = sB + s_cur * BSZ;
        #pragma unroll
        for (int ks = 0; ks < 2; ++ks) {
            uint32_t af[4][4];
            #pragma unroll
            for (int mf = 0; mf < 4; ++mf)
                ldsm4(af[mf][0], af[mf][1], af[mf][2], af[mf][3],
                      &ca[a_base + mf * 16 * LDS + ks * 16]);

            if (EPI == 4 && wn == 0) {
                // A-frag rowsum: lane(l&3)=j covers k {2j,2j+1,2j+8,2j+9};
                // union over j is the full k16 -> exact row sums after shfl.
                #pragma unroll
                for (int mf = 0; mf < 4; ++mf) {
                    rsum[mf][0] += hsum2(af[mf][0]) + hsum2(af[mf][2]);
                    rsum[mf][1] += hsum2(af[mf][1]) + hsum2(af[mf][3]);
                }
            }

            uint32_t bg[8][2];
            #pragma unroll
            for (int pr = 0; pr < 4; ++pr)
                ldsm4(bg[2 * pr][0], bg[2 * pr][1], bg[2 * pr + 1][0], bg[2 * pr + 1][1],
                      &cb[b_base + pr * 16 * LDS + ks * 16]);
            #pragma unroll
            for (int mf = 0; mf < 4; ++mf)
                #pragma unroll
                for (int nf = 0; nf < 8; ++nf)
                    mma_f16(acc[mf][nf], af[mf], bg[nf]);
        }

        s_cur  = (s_cur == STAGES - 1)  ? 0 : s_cur + 1;
        s_nxt2 = (s_nxt2 == STAGES - 1) ? 0 : s_nxt2 + 1;
    }

    if (EPI == 4) {
        if (wn == 0) {
            #pragma unroll
            for (int mf = 0; mf < 4; ++mf) {
                #pragma unroll
                for (int h = 0; h < 2; ++h) {
                    float v = rsum[mf][h];
                    v += __shfl_xor_sync(0xffffffffu, v, 1);
                    v += __shfl_xor_sync(0xffffffffu, v, 2);
                    if ((lane & 3) == 0)
                        rs_sh[wm * 64 + mf * 16 + h * 8 + (lane >> 2)] = v;
                }
            }
        }
        __syncthreads();
    }

    const int r_base = bm0 + wm * 64 + (lane >> 2);
    const int c_base = bn0 + wn * 64 + ((lane & 3) << 1);

    #pragma unroll
    for (int mf = 0; mf < 4; ++mf) {
        #pragma unroll
        for (int nf = 0; nf < 8; ++nf) {
            const int r = r_base + mf * 16;
            const int c = c_base + nf * 8;
            float2 f0 = __half22float2(*(const __half2*)&acc[mf][nf][0]);
            float2 f1 = __half22float2(*(const __half2*)&acc[mf][nf][1]);

            if (EPI == 0) {
                f16* outp = (f16*)Cout + (size_t)z * sC_batch;
                const float b0 = (c < 512)     ? bias1[c]     : bias2[c - 512];
                const float b1 = (c + 1 < 512) ? bias1[c + 1] : bias2[c + 1 - 512];
                *(__half2*)(outp + (size_t)r * ldc + c) =
                    __floats2half2_rn(f0.x + b0, f0.y + b1);
                *(__half2*)(outp + (size_t)(r + 8) * ldc + c) =
                    __floats2half2_rn(f1.x + b0, f1.y + b1);
            } else if (EPI == 1) {
                f16* outp = (f16*)Cout + (size_t)z * sC_batch;
                const float rb0 = bias1[r];
                const float rb1 = bias1[r + 8];
                *(__half2*)(outp + (size_t)r * ldc + c) =
                    __floats2half2_rn(f0.x + rb0, f0.y + rb0);
                *(__half2*)(outp + (size_t)(r + 8) * ldc + c) =
                    __floats2half2_rn(f1.x + rb1, f1.y + rb1);
            } else if (EPI == 2) {
                f16* outp = (f16*)Cout + (size_t)z * sC_batch;
                *(__half2*)(outp + (size_t)r * ldc + c) =
                    __floats2half2_rn(__expf(f0.x * scale), __expf(f0.y * scale));
                *(__half2*)(outp + (size_t)(r + 8) * ldc + c) =
                    __floats2half2_rn(__expf(f1.x * scale), __expf(f1.y * scale));
            } else if (EPI == 4) {
                f16* outp = (f16*)Cout + (size_t)z * sC_batch;
                const float rs0 = 1.f / rs_sh[r - bm0];
                const float rs1 = 1.f / rs_sh[r + 8 - bm0];
                *(__half2*)(outp + (size_t)r * ldc + c) =
                    __floats2half2_rn(f0.x * rs0, f0.y * rs0);
                *(__half2*)(outp + (size_t)(r + 8) * ldc + c) =
                    __floats2half2_rn(f1.x * rs1, f1.y * rs1);
            } else {   // EPI == 3
                float* outp = (float*)Cout;
                const int bb = c >> 10;
                const int s  = c & 1023;
                const size_t i0 = (size_t)bb * (CH * HWDIM) + (size_t)r * HWDIM + s;
                const size_t i1 = i0 + 8 * HWDIM;
                const float br0 = bias1[r];
                const float br1 = bias1[r + 8];
                const float2 x0 = *(const float2*)(aux + i0);
                const float2 x1 = *(const float2*)(aux + i1);
                *(float2*)(outp + i0) = make_float2(f0.x * WO_UNSCALE + br0 + x0.x,
                                                    f0.y * WO_UNSCALE + br0 + x0.y);
                *(float2*)(outp + i1) = make_float2(f1.x * WO_UNSCALE + br1 + x1.x,
                                                    f1.y * WO_UNSCALE + br1 + x1.y);
            }
        }
    }
}

// ---------------- launch -----------------------------------------------------------
static constexpr int GEMM_SMEM = 3 * (128 * 40 + 256 * 40) * (int)sizeof(f16); // 92160

extern "C" void kernel_launch(void* const* d_in, const int* in_sizes, int n_in,
                              void* d_out, int out_size)
{
    (void)in_sizes; (void)n_in; (void)out_size;
    const float* x  = (const float*)d_in[0];
    const float* Wq = (const float*)d_in[1];
    const float* bq = (const float*)d_in[2];
    const float* Wk = (const float*)d_in[3];
    const float* bk = (const float*)d_in[4];
    const float* Wv = (const float*)d_in[5];
    const float* bv = (const float*)d_in[6];
    const float* Wo = (const float*)d_in[7];
    const float* bo = (const float*)d_in[8];
    float* out = (float*)d_out;

    f16 *pW, *pXT, *pQK, *pV, *pP, *pHT;
    cudaGetSymbolAddress((void**)&pW,  g_W);
    cudaGetSymbolAddress((void**)&pXT, g_XT);
    cudaGetSymbolAddress((void**)&pQK, g_QK);
    cudaGetSymbolAddress((void**)&pV,  g_V);
    cudaGetSymbolAddress((void**)&pP,  g_P);
    cudaGetSymbolAddress((void**)&pHT, g_HT);

    cudaFuncSetAttribute(gemm_kernel<0>, cudaFuncAttributeMaxDynamicSharedMemorySize, GEMM_SMEM);
    cudaFuncSetAttribute(gemm_kernel<1>, cudaFuncAttributeMaxDynamicSharedMemorySize, GEMM_SMEM);
    cudaFuncSetAttribute(gemm_kernel<2>, cudaFuncAttributeMaxDynamicSharedMemorySize, GEMM_SMEM);
    cudaFuncSetAttribute(gemm_kernel<3>, cudaFuncAttributeMaxDynamicSharedMemorySize, GEMM_SMEM);
    cudaFuncSetAttribute(gemm_kernel<4>, cudaFuncAttributeMaxDynamicSharedMemorySize, GEMM_SMEM);

    // prep
    convert_w_kernel<<<(CH * CH) / 256, 256>>>(Wq, Wk, Wv, Wo, pW);
    xt_kernel<<<dim3(HWDIM / 32, CH / 32, BATCH), dim3(32, 32)>>>(x, pXT);

    // QK = XT * [Wq|Wk]^T : M=32768, N=1024, K=512
    gemm_kernel<0><<<dim3(1024 / 256, NALL / 128, 1), 256, GEMM_SMEM>>>(
        pXT, pW, pQK, CH, CH, CH, 1024, 0, 0, 0, bq, bk, nullptr, 1.f);

    // V = Wv * X^T (+bv rows) : M=512, N=32768 -> [c][token]
    gemm_kernel<1><<<dim3(NALL / 256, CH / 128, 1), 256, GEMM_SMEM>>>(
        pW + 2 * CH * CH, pXT, pV, CH, CH, CH, NALL, 0, 0, 0, bv, nullptr, nullptr, 1.f);

    // P_b = exp(scale * Q_b K_b^T) : per batch, M=N=1024, K=512
    gemm_kernel<2><<<dim3(1024 / 256, HWDIM / 128, BATCH), 256, GEMM_SMEM>>>(
        pQK, pQK + 512, pP, CH, 1024, 1024, HWDIM,
        (size_t)HWDIM * 1024, (size_t)HWDIM * 1024, (size_t)HWDIM * HWDIM,
        nullptr, nullptr, nullptr, 0.04419417382415922f);

    // HT_b = (P_b * V_b^T) / rowsum(P_b)  : M=1024, N=512, K=1024
    // (denominators computed inline from A fragments)
    gemm_kernel<4><<<dim3(CH / 256, HWDIM / 128, BATCH), 256, GEMM_SMEM>>>(
        pP, pV, pHT, HWDIM, HWDIM, NALL, CH,
        (size_t)HWDIM * HWDIM, (size_t)HWDIM, (size_t)HWDIM * CH,
        nullptr, nullptr, nullptr, 1.f);

    // O = Wo_scaled * HT^T, unscale + bo + x : M=512, N=32768 -> [B][C][H][W]
    gemm_kernel<3><<<dim3(NALL / 256, CH / 128, 1), 256, GEMM_SMEM>>>(
        pW + 3 * CH * CH, pHT, out, CH, CH, CH, 0,
        0, 0, 0, bo, nullptr, x, 1.f);
}

// round 9
// speedup vs baseline: 1.2335x; 1.1885x over previous
#include <cuda_runtime.h>
#include <cuda_fp16.h>
#include <cstdint>

using f16 = __half;
#define DEVINLINE __device__ __forceinline__

static constexpr int CH    = 512;
static constexpr int HWDIM = 1024;
static constexpr int BATCH = 32;
static constexpr int NALL  = BATCH * HWDIM;   // 32768

static constexpr float WO_SCALE   = 4096.f;
static constexpr float WO_UNSCALE = 1.f / 4096.f;
static constexpr float SCALE_S    = 0.04419417382415922f;  // 512^-0.5

// ---------------- scratch ----------------------------------------------------
// g_W slots: 0=WkT, 1=WqT, 2=Wo_s(row-major, x4096), 3=WvT
__device__ f16   g_W [4 * CH * CH];
__device__ f16   g_M [2 * CH * CH];                  // 0=MsT, 1=Mo
__device__ f16   g_XT[(size_t)NALL * CH];            // [token][c]
__device__ f16   g_T [(size_t)NALL * CH];            // [token][c']  = X*Ms
__device__ f16   g_U [(size_t)CH * NALL];            // [r][token]   = Mo*X^T
__device__ f16   g_P [(size_t)BATCH * HWDIM * HWDIM];
__device__ float g_A1[CH], g_A2[CH], g_WOBV[CH], g_CST[1];
__device__ float g_SU[NALL], g_SW[NALL];

// ---------------- helpers ------------------------------------------------------
DEVINLINE void ldsm4(uint32_t& r0, uint32_t& r1, uint32_t& r2, uint32_t& r3,
                     const f16* p) {
    uint32_t addr = (uint32_t)__cvta_generic_to_shared(p);
    asm volatile("ldmatrix.sync.aligned.m8n8.x4.shared.b16 {%0,%1,%2,%3}, [%4];"
                 : "=r"(r0), "=r"(r1), "=r"(r2), "=r"(r3) : "r"(addr));
}

DEVINLINE void mma_f16(uint32_t c[2], const uint32_t a[4], const uint32_t b[2]) {
    asm volatile("mma.sync.aligned.m16n8k16.row.col.f16.f16.f16.f16 "
                 "{%0,%1},{%2,%3,%4,%5},{%6,%7},{%0,%1};"
                 : "+r"(c[0]), "+r"(c[1])
                 : "r"(a[0]), "r"(a[1]), "r"(a[2]), "r"(a[3]),
                   "r"(b[0]), "r"(b[1]));
}

DEVINLINE void cp16(f16* dst, const f16* src) {
    uint32_t d = (uint32_t)__cvta_generic_to_shared(dst);
    asm volatile("cp.async.cg.shared.global [%0], [%1], 16;" :: "r"(d), "l"(src));
}
DEVINLINE void cp_commit() { asm volatile("cp.async.commit_group;"); }
template<int N> DEVINLINE void cp_wait() {
    asm volatile("cp.async.wait_group %0;" :: "n"(N));
}

DEVINLINE float hsum2(uint32_t h) {
    float2 f = __half22float2(*reinterpret_cast<const __half2*>(&h));
    return f.x + f.y;
}

// ---------------- prep kernels ---------------------------------------------------
// z=0: WkT<-Wk  z=1: WqT<-Wq  z=2: Wo_s copy(x4096)  z=3: WvT<-Wv
__global__ void convert_w_kernel(const float* __restrict__ wq, const float* __restrict__ wk,
                                 const float* __restrict__ wv, const float* __restrict__ wo,
                                 f16* __restrict__ W) {
    __shared__ float t[32][33];
    const int z = blockIdx.z;
    const float* src = (z == 0) ? wk : (z == 1) ? wq : (z == 2) ? wo : wv;
    f16* dst = W + (size_t)z * CH * CH;
    const int r0 = blockIdx.y * 32, c0 = blockIdx.x * 32;
    const int tx = threadIdx.x, ty = threadIdx.y;
    if (z == 2) {
        dst[(size_t)(r0 + ty) * CH + c0 + tx] =
            __float2half(src[(size_t)(r0 + ty) * CH + c0 + tx] * WO_SCALE);
    } else {
        t[ty][tx] = src[(size_t)(r0 + ty) * CH + c0 + tx];
        __syncthreads();
        dst[(size_t)(c0 + ty) * CH + r0 + tx] = __float2half(t[tx][ty]);
    }
}

// x [B][C][HW] fp32 -> XT [B*HW][C] f16
__global__ void xt_kernel(const float* __restrict__ x, f16* __restrict__ XT) {
    __shared__ float tile[32][33];
    const int b  = blockIdx.z;
    const int s0 = blockIdx.x * 32;
    const int c0 = blockIdx.y * 32;
    const int tx = threadIdx.x, ty = threadIdx.y;
    tile[ty][tx] = x[((size_t)b * CH + c0 + ty) * HWDIM + s0 + tx];
    __syncthreads();
    XT[((size_t)b * HWDIM + s0 + ty) * CH + c0 + tx] = __float2half(tile[tx][ty]);
}

// a1 = Wq^T bk, a2 = Wk^T bq, wobv = 4096 * Wo bv, cst = bq.bk
__global__ void biasvec_kernel(const float* __restrict__ wq, const float* __restrict__ wk,
                               const float* __restrict__ wo,
                               const float* __restrict__ bq, const float* __restrict__ bk,
                               const float* __restrict__ bv,
                               float* __restrict__ a1, float* __restrict__ a2,
                               float* __restrict__ wobv, float* __restrict__ cst) {
    const int i = blockIdx.x;
    const int t = threadIdx.x;          // 128 threads
    float s1 = 0.f, s2 = 0.f, s3 = 0.f, s4 = 0.f;
    for (int o = t; o < CH; o += 128) {
        s1 += wq[(size_t)o * CH + i] * bk[o];
        s2 += wk[(size_t)o * CH + i] * bq[o];
        s3 += wo[(size_t)i * CH + o] * bv[o];
        if (i == 0) s4 += bq[o] * bk[o];
    }
    __shared__ float sh[4][128];
    sh[0][t] = s1; sh[1][t] = s2; sh[2][t] = s3; sh[3][t] = s4;
    __syncthreads();
    for (int o = 64; o > 0; o >>= 1) {
        if (t < o) {
            sh[0][t] += sh[0][t + o]; sh[1][t] += sh[1][t + o];
            sh[2][t] += sh[2][t + o]; sh[3][t] += sh[3][t + o];
        }
        __syncthreads();
    }
    if (t == 0) {
        a1[i] = sh[0][0];
        a2[i] = sh[1][0];
        wobv[i] = sh[2][0] * WO_SCALE;
        if (i == 0) cst[0] = sh[3][0];
    }
}

// su[t] = SCALE_S*(XT[t].a1) + 0.5*SCALE_S*cst ; sw likewise with a2
__global__ void uw_kernel(const f16* __restrict__ XT,
                          const float* __restrict__ a1, const float* __restrict__ a2,
                          const float* __restrict__ cst,
                          float* __restrict__ su, float* __restrict__ sw) {
    const int tok  = blockIdx.x * 8 + (threadIdx.x >> 5);
    const int lane = threadIdx.x & 31;
    const __half2* xr = (const __half2*)(XT + (size_t)tok * CH);
    const float2* p1 = (const float2*)a1;
    const float2* p2 = (const float2*)a2;
    float s1 = 0.f, s2 = 0.f;
    #pragma unroll
    for (int j = lane; j < 256; j += 32) {
        float2 xv = __half22float2(xr[j]);
        float2 v1 = p1[j], v2 = p2[j];
        s1 += xv.x * v1.x + xv.y * v1.y;
        s2 += xv.x * v2.x + xv.y * v2.y;
    }
    #pragma unroll
    for (int o = 16; o > 0; o >>= 1) {
        s1 += __shfl_xor_sync(0xffffffffu, s1, o);
        s2 += __shfl_xor_sync(0xffffffffu, s2, o);
    }
    if (lane == 0) {
        const float half_c = 0.5f * SCALE_S * cst[0];
        su[tok] = SCALE_S * s1 + half_c;
        sw[tok] = SCALE_S * s2 + half_c;
    }
}

// ---------------- GEMM: C[m,n] = sum_k A[m,k]*B[n,k], f16 accum -----------------
// CTA tile 128x256 (BK=32); 8 warps of 64x64. 3-stage cp.async pipeline.
// EPI 1: f16 out, optional row bias (bias1 fp32, nullable)
// EPI 2: f16 out = exp(acc*scale + bias1[z*1024+r] + bias2[z*1024+c])
// EPI 5: fp32 out at [z][r][c]: acc * (1/colsum(B)) * WO_UNSCALE + bias1[r] + aux residual
template<int EPI>
__global__ void __launch_bounds__(256, 2)
gemm_kernel(const f16* __restrict__ A, const f16* __restrict__ B,
            void* __restrict__ Cout,
            int K, int lda, int ldb, int ldc,
            size_t sA_batch, size_t sB_batch, size_t sC_batch,
            const float* __restrict__ bias1, const float* __restrict__ bias2,
            const float* __restrict__ aux, float scale)
{
    constexpr int BM = 128, BN = 256, BK = 32;
    constexpr int STAGES = 3;
    constexpr int LDS = BK + 8;
    constexpr int ASZ = BM * LDS;
    constexpr int BSZ = BN * LDS;
    extern __shared__ f16 smem[];
    f16* sA = smem;
    f16* sB = smem + STAGES * ASZ;

    __shared__ float cs_sh[BN];   // column sums (EPI 5)

    const int tid  = threadIdx.x;
    const int lane = tid & 31;
    const int warp = tid >> 5;
    const int wm   = warp >> 2;
    const int wn   = warp & 3;
    const int bm0  = blockIdx.y * BM;
    const int bn0  = blockIdx.x * BN;
    const int z    = blockIdx.z;

    const f16* Ab = A + (size_t)z * sA_batch;
    const f16* Bb = B + (size_t)z * sB_batch;

    const int arow = tid >> 1;
    const int acol = (tid & 1) * 16;
    const int brow = tid >> 2;
    const int bcol = (tid & 3) * 8;

    const f16* gA = Ab + (size_t)(bm0 + arow) * lda + acol;
    const f16* gB = Bb + (size_t)(bn0 + brow) * ldb + bcol;
    f16* swA = sA + arow * LDS + acol;
    f16* swB = sB + brow * LDS + bcol;

    const int nk = K / BK;

    auto load_stage = [&](int stg, int kt) {
        const int ko = kt * BK;
        f16* dA = swA + stg * ASZ;
        f16* dB = swB + stg * BSZ;
        cp16(dA,     gA + ko);
        cp16(dA + 8, gA + ko + 8);
        #pragma unroll
        for (int i = 0; i < 4; ++i)
            cp16(dB + i * 64 * LDS, gB + (size_t)i * 64 * ldb + ko);
        cp_commit();
    };

    load_stage(0, 0);
    load_stage(1, 1);          // nk >= 16 always here

    uint32_t acc[4][8][2];
    #pragma unroll
    for (int i = 0; i < 4; ++i)
        #pragma unroll
        for (int j = 0; j < 8; ++j) { acc[i][j][0] = 0u; acc[i][j][1] = 0u; }

    float bsum[8];
    if (EPI == 5) {
        #pragma unroll
        for (int i = 0; i < 8; ++i) bsum[i] = 0.f;
    }

    const int a_base = (wm * 64 + (lane & 15)) * LDS + (lane >> 4) * 8;
    const int b_base = (wn * 64 + (lane & 7) + ((lane >> 4) & 1) * 8) * LDS
                     + ((lane >> 3) & 1) * 8;

    int s_cur = 0, s_nxt2 = 2;

    for (int kt = 0; kt < nk; ++kt) {
        if (kt + 2 <= nk) cp_wait<1>(); else cp_wait<0>();
        __syncthreads();

        if (kt + 2 < nk) load_stage(s_nxt2, kt + 2);

        const f16* ca = sA + s_cur * ASZ;
        const f16* cb = sB + s_cur * BSZ;
        #pragma unroll
        for (int ks = 0; ks < 2; ++ks) {
            uint32_t af[4][4];
            #pragma unroll
            for (int mf = 0; mf < 4; ++mf)
                ldsm4(af[mf][0], af[mf][1], af[mf][2], af[mf][3],
                      &ca[a_base + mf * 16 * LDS + ks * 16]);
            uint32_t bg[8][2];
            #pragma unroll
            for (int pr = 0; pr < 4; ++pr)
                ldsm4(bg[2 * pr][0], bg[2 * pr][1], bg[2 * pr + 1][0], bg[2 * pr + 1][1],
                      &cb[b_base + pr * 16 * LDS + ks * 16]);

            if (EPI == 5 && wm == 0) {
                // per-lane partial column sums of B (rows of B = C columns)
                #pragma unroll
                for (int nf = 0; nf < 8; ++nf)
                    bsum[nf] += hsum2(bg[nf][0]) + hsum2(bg[nf][1]);
            }

            #pragma unroll
            for (int mf = 0; mf < 4; ++mf)
                #pragma unroll
                for (int nf = 0; nf < 8; ++nf)
                    mma_f16(acc[mf][nf], af[mf], bg[nf]);
        }

        s_cur  = (s_cur == STAGES - 1)  ? 0 : s_cur + 1;
        s_nxt2 = (s_nxt2 == STAGES - 1) ? 0 : s_nxt2 + 1;
    }

    if (EPI == 5) {
        if (wm == 0) {
            #pragma unroll
            for (int nf = 0; nf < 8; ++nf) {
                float v = bsum[nf];
                v += __shfl_xor_sync(0xffffffffu, v, 1);
                v += __shfl_xor_sync(0xffffffffu, v, 2);
                if ((lane & 3) == 0)
                    cs_sh[wn * 64 + (nf >> 1) * 16 + (nf & 1) * 8 + (lane >> 2)] = v;
            }
        }
        __syncthreads();
    }

    const int r_base = bm0 + wm * 64 + (lane >> 2);
    const int c_base = bn0 + wn * 64 + ((lane & 3) << 1);

    #pragma unroll
    for (int mf = 0; mf < 4; ++mf) {
        #pragma unroll
        for (int nf = 0; nf < 8; ++nf) {
            const int r = r_base + mf * 16;
            const int c = c_base + nf * 8;
            float2 f0 = __half22float2(*(const __half2*)&acc[mf][nf][0]); // (r, c/c+1)
            float2 f1 = __half22float2(*(const __half2*)&acc[mf][nf][1]); // (r+8, c/c+1)

            if (EPI == 1) {
                f16* outp = (f16*)Cout + (size_t)z * sC_batch;
                const float rb0 = bias1 ? bias1[r] : 0.f;
                const float rb1 = bias1 ? bias1[r + 8] : 0.f;
                *(__half2*)(outp + (size_t)r * ldc + c) =
                    __floats2half2_rn(f0.x + rb0, f0.y + rb0);
                *(__half2*)(outp + (size_t)(r + 8) * ldc + c) =
                    __floats2half2_rn(f1.x + rb1, f1.y + rb1);
            } else if (EPI == 2) {
                f16* outp = (f16*)Cout + (size_t)z * sC_batch;
                const float su0 = bias1[z * HWDIM + r];
                const float su1 = bias1[z * HWDIM + r + 8];
                const float sw0 = bias2[z * HWDIM + c];
                const float sw1 = bias2[z * HWDIM + c + 1];
                *(__half2*)(outp + (size_t)r * ldc + c) =
                    __floats2half2_rn(__expf(f0.x * scale + su0 + sw0),
                                      __expf(f0.y * scale + su0 + sw1));
                *(__half2*)(outp + (size_t)(r + 8) * ldc + c) =
                    __floats2half2_rn(__expf(f1.x * scale + su1 + sw0),
                                      __expf(f1.y * scale + su1 + sw1));
            } else {   // EPI == 5 : final fp32 out + residual, column-normalized
                float* outp = (float*)Cout;
                const float inv0 = WO_UNSCALE / cs_sh[c - bn0];
                const float inv1 = WO_UNSCALE / cs_sh[c + 1 - bn0];
                const size_t i0 = (size_t)z * (CH * HWDIM) + (size_t)r * HWDIM + c;
                const size_t i1 = i0 + 8 * HWDIM;
                const float br0 = bias1 ? bias1[r] : 0.f;
                const float br1 = bias1 ? bias1[r + 8] : 0.f;
                const float2 x0 = *(const float2*)(aux + i0);
                const float2 x1 = *(const float2*)(aux + i1);
                *(float2*)(outp + i0) = make_float2(f0.x * inv0 + br0 + x0.x,
                                                    f0.y * inv1 + br0 + x0.y);
                *(float2*)(outp + i1) = make_float2(f1.x * inv0 + br1 + x1.x,
                                                    f1.y * inv1 + br1 + x1.y);
            }
        }
    }
}

// ---------------- launch -----------------------------------------------------------
static constexpr int GEMM_SMEM = 3 * (128 * 40 + 256 * 40) * (int)sizeof(f16); // 92160

extern "C" void kernel_launch(void* const* d_in, const int* in_sizes, int n_in,
                              void* d_out, int out_size)
{
    (void)in_sizes; (void)n_in; (void)out_size;
    const float* x  = (const float*)d_in[0];
    const float* Wq = (const float*)d_in[1];
    const float* bq = (const float*)d_in[2];
    const float* Wk = (const float*)d_in[3];
    const float* bk = (const float*)d_in[4];
    const float* Wv = (const float*)d_in[5];
    const float* bv = (const float*)d_in[6];
    const float* Wo = (const float*)d_in[7];
    const float* bo = (const float*)d_in[8];
    float* out = (float*)d_out;

    f16 *pW, *pM, *pXT, *pT, *pU, *pP;
    float *pA1, *pA2, *pWOBV, *pCST, *pSU, *pSW;
    cudaGetSymbolAddress((void**)&pW,   g_W);
    cudaGetSymbolAddress((void**)&pM,   g_M);
    cudaGetSymbolAddress((void**)&pXT,  g_XT);
    cudaGetSymbolAddress((void**)&pT,   g_T);
    cudaGetSymbolAddress((void**)&pU,   g_U);
    cudaGetSymbolAddress((void**)&pP,   g_P);
    cudaGetSymbolAddress((void**)&pA1,  g_A1);
    cudaGetSymbolAddress((void**)&pA2,  g_A2);
    cudaGetSymbolAddress((void**)&pWOBV,g_WOBV);
    cudaGetSymbolAddress((void**)&pCST, g_CST);
    cudaGetSymbolAddress((void**)&pSU,  g_SU);
    cudaGetSymbolAddress((void**)&pSW,  g_SW);

    cudaFuncSetAttribute(gemm_kernel<1>, cudaFuncAttributeMaxDynamicSharedMemorySize, GEMM_SMEM);
    cudaFuncSetAttribute(gemm_kernel<2>, cudaFuncAttributeMaxDynamicSharedMemorySize, GEMM_SMEM);
    cudaFuncSetAttribute(gemm_kernel<5>, cudaFuncAttributeMaxDynamicSharedMemorySize, GEMM_SMEM);

    // prep
    convert_w_kernel<<<dim3(16, 16, 4), dim3(32, 32)>>>(Wq, Wk, Wv, Wo, pW);
    xt_kernel<<<dim3(HWDIM / 32, CH / 32, BATCH), dim3(32, 32)>>>(x, pXT);
    biasvec_kernel<<<CH, 128>>>(Wq, Wk, Wo, bq, bk, bv, pA1, pA2, pWOBV, pCST);
    uw_kernel<<<NALL / 8, 256>>>(pXT, pA1, pA2, pCST, pSU, pSW);

    // MsT = Wk^T Wq (z=0), Mo = Wo_s Wv (z=1): M=N=K=512
    gemm_kernel<1><<<dim3(2, 4, 2), 256, GEMM_SMEM>>>(
        pW, pW + CH * CH, pM, CH, CH, CH, CH,
        (size_t)2 * CH * CH, (size_t)2 * CH * CH, (size_t)CH * CH,
        nullptr, nullptr, nullptr, 1.f);

    // T = X * Ms : M=32768, N=512, K=512  (B = MsT)
    gemm_kernel<1><<<dim3(2, NALL / 128, 1), 256, GEMM_SMEM>>>(
        pXT, pM, pT, CH, CH, CH, CH, 0, 0, 0,
        nullptr, nullptr, nullptr, 1.f);

    // U = Mo * X^T (+wobv rows) : M=512, N=32768, K=512 -> [r][token]
    gemm_kernel<1><<<dim3(NALL / 256, 4, 1), 256, GEMM_SMEM>>>(
        pM + CH * CH, pXT, pU, CH, CH, CH, NALL, 0, 0, 0,
        pWOBV, nullptr, nullptr, 1.f);

    // P_b = exp(scale*T_b X_b^T + su_i + sw_j) : per batch M=N=1024, K=512
    gemm_kernel<2><<<dim3(4, 8, BATCH), 256, GEMM_SMEM>>>(
        pT, pXT, pP, CH, CH, CH, HWDIM,
        (size_t)HWDIM * CH, (size_t)HWDIM * CH, (size_t)HWDIM * HWDIM,
        pSU, pSW, nullptr, SCALE_S);

    // O_b = U_b P_b^T / colsum + bo + x : M=512, N=1024, K=1024 per batch
    gemm_kernel<5><<<dim3(4, 4, BATCH), 256, GEMM_SMEM>>>(
        pU, pP, out, HWDIM, NALL, HWDIM, HWDIM,
        (size_t)HWDIM, (size_t)HWDIM * HWDIM, 0,
        bo, nullptr, x, 1.f);
}